// round 4
// baseline (speedup 1.0000x reference)
#include <cuda_runtime.h>
#include <cuda_bf16.h>
#include <cstddef>

// ---------------------------------------------------------------------------
// Model_53901839564895: CNN forward
//   x [512,3,128,128]
//   conv1 5x5 pad1 (3->5) -> relu -> BN(eval, mean=0,var=1) -> maxpool 3,2,1
//   conv2 3x3 pad1 (5->9) -> relu -> maxpool 3,2,1
//   conv3 3x3 pad1 (9->16) -> flatten -> FC(16384->6) -> softmax
// Weight layout quirk: effective weight = raw buffer indexed as
//   w[((c*KH+ki)*KW+kj)*COUT + o]
// ---------------------------------------------------------------------------

#define BATCH 512

// Static scratch (allocation-free rule): p1 [512,5,63,63], p2 [512,9,32,32]
__device__ float g_p1[(size_t)BATCH * 5 * 63 * 63];
__device__ float g_p2[(size_t)BATCH * 9 * 32 * 32];

// ===========================================================================
// K1: conv1(5x5,pad1) + relu + BN + maxpool(3,2,1): 128x128 -> conv 126x126 -> pool 63x63
// Block handles a 16x16 tile of pooled outputs for one image.
// grid (4,4,512), block 256.
// ===========================================================================
__global__ __launch_bounds__(256) void k1_conv_bn_pool(
    const float* __restrict__ x, const float* __restrict__ k1,
    const float* __restrict__ gamma, const float* __restrict__ beta)
{
    __shared__ float sw[375];            // 5x5x3x5
    __shared__ float sscale[5], sbeta[5];
    __shared__ float sin[3][37][37];     // input halo tile
    __shared__ float sconv[5][33][33];   // post-BN conv tile (0 where pool-pad)

    const int tid = threadIdx.x;
    const int b   = blockIdx.z;
    const int px0 = blockIdx.x * 16;
    const int py0 = blockIdx.y * 16;
    const int cy0 = 2 * py0 - 1;         // conv-row origin of tile (pool pad 1)
    const int cx0 = 2 * px0 - 1;

    // FIX: strided loop (375 > 256 threads; old guarded load left sw[256..374]
    // uninitialized -> rel_err 0.29)
    for (int i = tid; i < 375; i += 256) sw[i] = k1[i];
    if (tid < 5) {
        sscale[tid] = gamma[tid] * rsqrtf(1.0f + 1e-5f);
        sbeta[tid]  = beta[tid];
    }

    // Load input halo: rows cy0-1 .. cy0+35 (conv pad 1, kernel 5)
    const float* xb = x + (size_t)b * 3 * 128 * 128;
    for (int idx = tid; idx < 3 * 37 * 37; idx += 256) {
        int c = idx / (37 * 37);
        int r = idx % (37 * 37);
        int li = r / 37, lj = r % 37;
        int iy = cy0 - 1 + li, ix = cx0 - 1 + lj;
        float v = 0.0f;
        if (iy >= 0 && iy < 128 && ix >= 0 && ix < 128)
            v = xb[(c * 128 + iy) * 128 + ix];
        sin[c][li][lj] = v;
    }
    __syncthreads();

    // Conv: 33x33 outputs x 5 cout, register blocked (3 x-positions x 5 cout)
    for (int item = tid; item < 33 * 11; item += 256) {
        int y  = item / 11;
        int x0 = (item % 11) * 3;
        float acc[3][5];
        #pragma unroll
        for (int xi = 0; xi < 3; xi++)
            #pragma unroll
            for (int o = 0; o < 5; o++) acc[xi][o] = 0.0f;

        #pragma unroll
        for (int c = 0; c < 3; c++) {
            #pragma unroll
            for (int ki = 0; ki < 5; ki++) {
                float r[7];
                #pragma unroll
                for (int j = 0; j < 7; j++) r[j] = sin[c][y + ki][x0 + j];
                #pragma unroll
                for (int kj = 0; kj < 5; kj++) {
                    const float* wp = &sw[((c * 5 + ki) * 5 + kj) * 5];
                    #pragma unroll
                    for (int o = 0; o < 5; o++) {
                        float wv = wp[o];
                        acc[0][o] = fmaf(r[kj],     wv, acc[0][o]);
                        acc[1][o] = fmaf(r[kj + 1], wv, acc[1][o]);
                        acc[2][o] = fmaf(r[kj + 2], wv, acc[2][o]);
                    }
                }
            }
        }
        int cy = cy0 + y;
        bool yok = (cy >= 0 && cy < 126);
        #pragma unroll
        for (int xi = 0; xi < 3; xi++) {
            int cx = cx0 + x0 + xi;
            bool ok = yok && (cx >= 0) && (cx < 126);
            #pragma unroll
            for (int o = 0; o < 5; o++) {
                float v = 0.0f;  // zero pool-pad, matches reference zero padding
                if (ok) v = fmaf(fmaxf(acc[xi][o], 0.0f), sscale[o], sbeta[o]);
                sconv[o][y][x0 + xi] = v;
            }
        }
    }
    __syncthreads();

    // Maxpool 3x3 stride 2 (window taps all live in sconv; pads stored as 0)
    float* p1b = g_p1 + (size_t)b * 5 * 63 * 63;
    for (int idx = tid; idx < 5 * 256; idx += 256) {
        int o = idx >> 8, rem = idx & 255;
        int ly = rem >> 4, lx = rem & 15;
        int py = py0 + ly, px = px0 + lx;
        if (py < 63 && px < 63) {
            float m = -1e30f;
            #pragma unroll
            for (int dy = 0; dy < 3; dy++)
                #pragma unroll
                for (int dx = 0; dx < 3; dx++)
                    m = fmaxf(m, sconv[o][2 * ly + dy][2 * lx + dx]);
            p1b[(o * 63 + py) * 63 + px] = m;
        }
    }
}

// ===========================================================================
// K2: conv2(3x3,pad1, 5->9) + relu + maxpool(3,2,1): 63x63 -> 32x32
// Block handles 16x8 pooled tile. grid (2,4,512), block 256.
// ===========================================================================
__global__ __launch_bounds__(256) void k2_conv_pool(const float* __restrict__ k2)
{
    __shared__ float sw[405];            // 3x3x5x9
    __shared__ float sin[5][19][35];     // input halo: 17 conv rows + 2
    __shared__ float sconv[9][17][33];

    const int tid = threadIdx.x;
    const int b   = blockIdx.z;
    const int px0 = blockIdx.x * 16;
    const int py0 = blockIdx.y * 8;
    const int cy0 = 2 * py0 - 1;
    const int cx0 = 2 * px0 - 1;

    // FIX: strided loop (405 > 256 threads)
    for (int i = tid; i < 405; i += 256) sw[i] = k2[i];

    const float* pin = g_p1 + (size_t)b * 5 * 63 * 63;
    for (int idx = tid; idx < 5 * 19 * 35; idx += 256) {
        int c = idx / (19 * 35);
        int r = idx % (19 * 35);
        int li = r / 35, lj = r % 35;
        int iy = cy0 - 1 + li, ix = cx0 - 1 + lj;
        float v = 0.0f;
        if (iy >= 0 && iy < 63 && ix >= 0 && ix < 63)
            v = pin[(c * 63 + iy) * 63 + ix];
        sin[c][li][lj] = v;
    }
    __syncthreads();

    // Conv: 17x33 outputs x 9 cout, register blocked (3 x-pos x 9 cout)
    for (int item = tid; item < 17 * 11; item += 256) {
        int y  = item / 11;
        int x0 = (item % 11) * 3;
        float acc[3][9];
        #pragma unroll
        for (int xi = 0; xi < 3; xi++)
            #pragma unroll
            for (int o = 0; o < 9; o++) acc[xi][o] = 0.0f;

        #pragma unroll
        for (int c = 0; c < 5; c++) {
            #pragma unroll
            for (int ki = 0; ki < 3; ki++) {
                float r[5];
                #pragma unroll
                for (int j = 0; j < 5; j++) r[j] = sin[c][y + ki][x0 + j];
                #pragma unroll
                for (int kj = 0; kj < 3; kj++) {
                    const float* wp = &sw[((c * 3 + ki) * 3 + kj) * 9];
                    #pragma unroll
                    for (int o = 0; o < 9; o++) {
                        float wv = wp[o];
                        acc[0][o] = fmaf(r[kj],     wv, acc[0][o]);
                        acc[1][o] = fmaf(r[kj + 1], wv, acc[1][o]);
                        acc[2][o] = fmaf(r[kj + 2], wv, acc[2][o]);
                    }
                }
            }
        }
        int cy = cy0 + y;
        bool yok = (cy >= 0 && cy < 63);
        #pragma unroll
        for (int xi = 0; xi < 3; xi++) {
            int cx = cx0 + x0 + xi;
            bool ok = yok && (cx >= 0) && (cx < 63);
            #pragma unroll
            for (int o = 0; o < 9; o++) {
                float v = 0.0f;
                if (ok) v = fmaxf(acc[xi][o], 0.0f);
                sconv[o][y][x0 + xi] = v;
            }
        }
    }
    __syncthreads();

    float* p2b = g_p2 + (size_t)b * 9 * 32 * 32;
    for (int idx = tid; idx < 9 * 128; idx += 256) {
        int o = idx / 128, rem = idx % 128;
        int ly = rem >> 4, lx = rem & 15;
        int py = py0 + ly, px = px0 + lx;   // always < 32
        float m = -1e30f;
        #pragma unroll
        for (int dy = 0; dy < 3; dy++)
            #pragma unroll
            for (int dx = 0; dx < 3; dx++)
                m = fmaxf(m, sconv[o][2 * ly + dy][2 * lx + dx]);
        p2b[(o * 32 + py) * 32 + px] = m;
    }
}

// ===========================================================================
// K3: conv3(3x3,pad1, 9->16) + FC(16384->6) + softmax. One block per image.
// Thread t owns 4 consecutive x positions at row y = t/8, all 16 couts:
// 64 conv outputs in registers, FC accumulated directly (conv3 never stored).
// grid (512), block 256.
// ===========================================================================
__global__ __launch_bounds__(256) void k3_conv_fc_softmax(
    const float* __restrict__ k3, const float* __restrict__ fc_w,
    const float* __restrict__ fc_b, float* __restrict__ out)
{
    __shared__ float sin[9 * 32 * 32];   // 9216
    __shared__ float sw[1296];           // 3x3x9x16
    __shared__ float sred[8 * 6];
    __shared__ float slog[6];

    const int tid = threadIdx.x;
    const int b   = blockIdx.x;

    const float* pin = g_p2 + (size_t)b * 9 * 1024;
    for (int idx = tid; idx < 9216; idx += 256) sin[idx] = pin[idx];
    for (int idx = tid; idx < 1296; idx += 256) sw[idx] = k3[idx];
    __syncthreads();

    const int y  = tid >> 3;
    const int x0 = (tid & 7) * 4;

    float cacc[4][16];
    #pragma unroll
    for (int xi = 0; xi < 4; xi++)
        #pragma unroll
        for (int o = 0; o < 16; o++) cacc[xi][o] = 0.0f;

    for (int c = 0; c < 9; c++) {
        #pragma unroll
        for (int ki = 0; ki < 3; ki++) {
            int iy = y + ki - 1;
            float r[6];
            #pragma unroll
            for (int j = 0; j < 6; j++) {
                int ix = x0 - 1 + j;
                r[j] = (iy >= 0 && iy < 32 && ix >= 0 && ix < 32)
                           ? sin[(c * 32 + iy) * 32 + ix] : 0.0f;
            }
            #pragma unroll
            for (int kj = 0; kj < 3; kj++) {
                const float* wp = &sw[((c * 3 + ki) * 3 + kj) * 16];
                #pragma unroll
                for (int o = 0; o < 16; o++) {
                    float wv = wp[o];
                    #pragma unroll
                    for (int xi = 0; xi < 4; xi++)
                        cacc[xi][o] = fmaf(r[xi + kj], wv, cacc[xi][o]);
                }
            }
        }
    }

    // FC: flat index f = o*1024 + y*32 + x0 + xi ; vectorized fc_w reads
    float facc[6];
    #pragma unroll
    for (int j = 0; j < 6; j++) facc[j] = 0.0f;
    const int base = y * 32 + x0;
    #pragma unroll
    for (int j = 0; j < 6; j++) {
        const float* wj = fc_w + (size_t)j * 16384 + base;
        #pragma unroll
        for (int o = 0; o < 16; o++) {
            float4 w4 = *reinterpret_cast<const float4*>(wj + o * 1024);
            facc[j] = fmaf(cacc[0][o], w4.x,
                      fmaf(cacc[1][o], w4.y,
                      fmaf(cacc[2][o], w4.z,
                      fmaf(cacc[3][o], w4.w, facc[j]))));
        }
    }

    // Warp reduce then block reduce
    #pragma unroll
    for (int j = 0; j < 6; j++) {
        float v = facc[j];
        #pragma unroll
        for (int off = 16; off > 0; off >>= 1)
            v += __shfl_down_sync(0xffffffffu, v, off);
        if ((tid & 31) == 0) sred[(tid >> 5) * 6 + j] = v;
    }
    __syncthreads();
    if (tid < 6) {
        float s = fc_b[tid];
        #pragma unroll
        for (int w = 0; w < 8; w++) s += sred[w * 6 + tid];
        slog[tid] = s;
    }
    __syncthreads();
    if (tid == 0) {
        float mx = slog[0];
        #pragma unroll
        for (int j = 1; j < 6; j++) mx = fmaxf(mx, slog[j]);
        float e[6], s = 0.0f;
        #pragma unroll
        for (int j = 0; j < 6; j++) { e[j] = expf(slog[j] - mx); s += e[j]; }
        float inv = 1.0f / s;
        #pragma unroll
        for (int j = 0; j < 6; j++) out[b * 6 + j] = e[j] * inv;
    }
}

// ===========================================================================
extern "C" void kernel_launch(void* const* d_in, const int* in_sizes, int n_in,
                              void* d_out, int out_size)
{
    const float* x     = (const float*)d_in[0];
    const float* k1    = (const float*)d_in[1];
    const float* gamma = (const float*)d_in[2];
    const float* beta  = (const float*)d_in[3];
    const float* k2    = (const float*)d_in[4];
    const float* k3    = (const float*)d_in[5];
    const float* fc_w  = (const float*)d_in[6];
    const float* fc_b  = (const float*)d_in[7];
    float* out = (float*)d_out;

    k1_conv_bn_pool<<<dim3(4, 4, BATCH), 256>>>(x, k1, gamma, beta);
    k2_conv_pool<<<dim3(2, 4, BATCH), 256>>>(k2);
    k3_conv_fc_softmax<<<BATCH, 256>>>(k3, fc_w, fc_b, out);
}

// round 5
// speedup vs baseline: 2.2152x; 2.2152x over previous
#include <cuda_runtime.h>
#include <cuda_bf16.h>
#include <cstddef>

// ---------------------------------------------------------------------------
// Model_53901839564895: CNN forward
//   x [512,3,128,128]
//   conv1 5x5 pad1 (3->5) -> relu -> BN(eval) -> maxpool 3,2,1   -> [512,5,63,63]
//   conv2 3x3 pad1 (5->9) -> relu -> maxpool 3,2,1               -> [512,9,32,32]
//   conv3 3x3 pad1 (9->16) -> flatten -> FC(16384->6) -> softmax
// Weight layout quirk: effective weight = raw buffer indexed as
//   w[((c*KH+ki)*KW+kj)*COUT + o]
// ---------------------------------------------------------------------------

#define BATCH 512

// Static scratch: p1 [512,5,63,63], p2 [512,9,32,32]
__device__ float g_p1[(size_t)BATCH * 5 * 63 * 63];
__device__ float g_p2[(size_t)BATCH * 9 * 32 * 32];

// ===========================================================================
// K1: conv1(5x5,pad1)+relu+BN+maxpool(3,2,1).
// Pooled tile 16x8 per block -> conv tile 33x17 -> 187 work items.
// 192 threads, ONE conv item per thread (no loop -> no unroll duplication,
// regs stay low, occupancy 4-5 CTAs/SM). grid (4,8,512).
// ===========================================================================
__global__ __launch_bounds__(192, 4) void k1_conv_bn_pool(
    const float* __restrict__ x, const float* __restrict__ k1,
    const float* __restrict__ gamma, const float* __restrict__ beta)
{
    __shared__ float sw[375];            // 5x5x3x5
    __shared__ float sscale[5], sbeta[5];
    __shared__ float sin[3][21][37];     // input halo: 17 conv rows + 4
    __shared__ float sconv[5][17][33];   // post-BN conv tile (0 where pad)

    const int tid = threadIdx.x;
    const int b   = blockIdx.z;
    const int px0 = blockIdx.x * 16;
    const int py0 = blockIdx.y * 8;
    const int cy0 = 2 * py0 - 1;         // conv-row origin (pool pad 1)
    const int cx0 = 2 * px0 - 1;

    for (int i = tid; i < 375; i += 192) sw[i] = k1[i];
    if (tid < 5) {
        sscale[tid] = gamma[tid] * rsqrtf(1.0f + 1e-5f);
        sbeta[tid]  = beta[tid];
    }

    // Input halo rows cy0-1 .. cy0+19 (conv pad 1, kernel 5)
    const float* xb = x + (size_t)b * 3 * 128 * 128;
    for (int idx = tid; idx < 3 * 21 * 37; idx += 192) {
        int c = idx / (21 * 37);
        int r = idx % (21 * 37);
        int li = r / 37, lj = r % 37;
        int iy = cy0 - 1 + li, ix = cx0 - 1 + lj;
        float v = 0.0f;
        if (iy >= 0 && iy < 128 && ix >= 0 && ix < 128)
            v = xb[(c * 128 + iy) * 128 + ix];
        sin[c][li][lj] = v;
    }
    __syncthreads();

    // One item per thread: y in [0,17), x-group of 3 in [0,11)
    if (tid < 187) {
        const int y  = tid / 11;
        const int x0 = (tid % 11) * 3;

        float acc[3][5];
        #pragma unroll
        for (int xi = 0; xi < 3; xi++)
            #pragma unroll
            for (int o = 0; o < 5; o++) acc[xi][o] = 0.0f;

        #pragma unroll
        for (int c = 0; c < 3; c++) {
            #pragma unroll
            for (int ki = 0; ki < 5; ki++) {
                float r[7];
                #pragma unroll
                for (int j = 0; j < 7; j++) r[j] = sin[c][y + ki][x0 + j];
                #pragma unroll
                for (int kj = 0; kj < 5; kj++) {
                    const float* wp = &sw[((c * 5 + ki) * 5 + kj) * 5];
                    #pragma unroll
                    for (int o = 0; o < 5; o++) {
                        float wv = wp[o];
                        acc[0][o] = fmaf(r[kj],     wv, acc[0][o]);
                        acc[1][o] = fmaf(r[kj + 1], wv, acc[1][o]);
                        acc[2][o] = fmaf(r[kj + 2], wv, acc[2][o]);
                    }
                }
            }
        }
        const int cy = cy0 + y;
        const bool yok = (cy >= 0 && cy < 126);
        #pragma unroll
        for (int xi = 0; xi < 3; xi++) {
            int cx = cx0 + x0 + xi;
            bool ok = yok && (cx >= 0) && (cx < 126);
            #pragma unroll
            for (int o = 0; o < 5; o++) {
                float v = 0.0f;  // zero pool-pad matches reference
                if (ok) v = fmaf(fmaxf(acc[xi][o], 0.0f), sscale[o], sbeta[o]);
                sconv[o][y][x0 + xi] = v;
            }
        }
    }
    __syncthreads();

    // Maxpool 3x3 stride 2 over the 16x8 pooled tile, 5 channels = 640 outs
    float* p1b = g_p1 + (size_t)b * 5 * 63 * 63;
    for (int idx = tid; idx < 5 * 128; idx += 192) {
        int o = idx >> 7, rem = idx & 127;
        int ly = rem >> 4, lx = rem & 15;
        int py = py0 + ly, px = px0 + lx;
        if (py < 63 && px < 63) {
            float m = -1e30f;
            #pragma unroll
            for (int dy = 0; dy < 3; dy++)
                #pragma unroll
                for (int dx = 0; dx < 3; dx++)
                    m = fmaxf(m, sconv[o][2 * ly + dy][2 * lx + dx]);
            p1b[(o * 63 + py) * 63 + px] = m;
        }
    }
}

// ===========================================================================
// K2: conv2(3x3,pad1, 5->9)+relu+maxpool(3,2,1): 63x63 -> 32x32.
// Pooled tile 16x8 -> conv 33x17 -> 187 items, 192 threads, one item/thread.
// grid (2,4,512).
// ===========================================================================
__global__ __launch_bounds__(192, 4) void k2_conv_pool(const float* __restrict__ k2)
{
    __shared__ float sw[405];            // 3x3x5x9
    __shared__ float sin[5][19][35];     // 17 conv rows + 2 halo
    __shared__ float sconv[9][17][33];

    const int tid = threadIdx.x;
    const int b   = blockIdx.z;
    const int px0 = blockIdx.x * 16;
    const int py0 = blockIdx.y * 8;
    const int cy0 = 2 * py0 - 1;
    const int cx0 = 2 * px0 - 1;

    for (int i = tid; i < 405; i += 192) sw[i] = k2[i];

    const float* pin = g_p1 + (size_t)b * 5 * 63 * 63;
    for (int idx = tid; idx < 5 * 19 * 35; idx += 192) {
        int c = idx / (19 * 35);
        int r = idx % (19 * 35);
        int li = r / 35, lj = r % 35;
        int iy = cy0 - 1 + li, ix = cx0 - 1 + lj;
        float v = 0.0f;
        if (iy >= 0 && iy < 63 && ix >= 0 && ix < 63)
            v = pin[(c * 63 + iy) * 63 + ix];
        sin[c][li][lj] = v;
    }
    __syncthreads();

    if (tid < 187) {
        const int y  = tid / 11;
        const int x0 = (tid % 11) * 3;

        float acc[3][9];
        #pragma unroll
        for (int xi = 0; xi < 3; xi++)
            #pragma unroll
            for (int o = 0; o < 9; o++) acc[xi][o] = 0.0f;

        #pragma unroll
        for (int c = 0; c < 5; c++) {
            #pragma unroll
            for (int ki = 0; ki < 3; ki++) {
                float r[5];
                #pragma unroll
                for (int j = 0; j < 5; j++) r[j] = sin[c][y + ki][x0 + j];
                #pragma unroll
                for (int kj = 0; kj < 3; kj++) {
                    const float* wp = &sw[((c * 3 + ki) * 3 + kj) * 9];
                    #pragma unroll
                    for (int o = 0; o < 9; o++) {
                        float wv = wp[o];
                        acc[0][o] = fmaf(r[kj],     wv, acc[0][o]);
                        acc[1][o] = fmaf(r[kj + 1], wv, acc[1][o]);
                        acc[2][o] = fmaf(r[kj + 2], wv, acc[2][o]);
                    }
                }
            }
        }
        const int cy = cy0 + y;
        const bool yok = (cy >= 0 && cy < 63);
        #pragma unroll
        for (int xi = 0; xi < 3; xi++) {
            int cx = cx0 + x0 + xi;
            bool ok = yok && (cx >= 0) && (cx < 63);
            #pragma unroll
            for (int o = 0; o < 9; o++) {
                float v = 0.0f;
                if (ok) v = fmaxf(acc[xi][o], 0.0f);
                sconv[o][y][x0 + xi] = v;
            }
        }
    }
    __syncthreads();

    float* p2b = g_p2 + (size_t)b * 9 * 32 * 32;
    for (int idx = tid; idx < 9 * 128; idx += 192) {
        int o = idx >> 7, rem = idx & 127;
        int ly = rem >> 4, lx = rem & 15;
        int py = py0 + ly, px = px0 + lx;   // always < 32
        float m = -1e30f;
        #pragma unroll
        for (int dy = 0; dy < 3; dy++)
            #pragma unroll
            for (int dx = 0; dx < 3; dx++)
                m = fmaxf(m, sconv[o][2 * ly + dy][2 * lx + dx]);
        p2b[(o * 32 + py) * 32 + px] = m;
    }
}

// ===========================================================================
// K3: conv3(3x3,pad1, 9->16) + FC(16384->6) + softmax. One block per image.
// Thread t owns 4 consecutive x positions at row y = t/8, all 16 couts.
// grid (512), block 256.
// ===========================================================================
__global__ __launch_bounds__(256) void k3_conv_fc_softmax(
    const float* __restrict__ k3, const float* __restrict__ fc_w,
    const float* __restrict__ fc_b, float* __restrict__ out)
{
    __shared__ float sin[9 * 32 * 32];   // 9216
    __shared__ float sw[1296];           // 3x3x9x16
    __shared__ float sred[8 * 6];
    __shared__ float slog[6];

    const int tid = threadIdx.x;
    const int b   = blockIdx.x;

    const float* pin = g_p2 + (size_t)b * 9 * 1024;
    for (int idx = tid; idx < 9216; idx += 256) sin[idx] = pin[idx];
    for (int idx = tid; idx < 1296; idx += 256) sw[idx] = k3[idx];
    __syncthreads();

    const int y  = tid >> 3;
    const int x0 = (tid & 7) * 4;

    float cacc[4][16];
    #pragma unroll
    for (int xi = 0; xi < 4; xi++)
        #pragma unroll
        for (int o = 0; o < 16; o++) cacc[xi][o] = 0.0f;

    for (int c = 0; c < 9; c++) {
        #pragma unroll
        for (int ki = 0; ki < 3; ki++) {
            int iy = y + ki - 1;
            float r[6];
            #pragma unroll
            for (int j = 0; j < 6; j++) {
                int ix = x0 - 1 + j;
                r[j] = (iy >= 0 && iy < 32 && ix >= 0 && ix < 32)
                           ? sin[(c * 32 + iy) * 32 + ix] : 0.0f;
            }
            #pragma unroll
            for (int kj = 0; kj < 3; kj++) {
                const float* wp = &sw[((c * 3 + ki) * 3 + kj) * 16];
                #pragma unroll
                for (int o = 0; o < 16; o++) {
                    float wv = wp[o];
                    #pragma unroll
                    for (int xi = 0; xi < 4; xi++)
                        cacc[xi][o] = fmaf(r[xi + kj], wv, cacc[xi][o]);
                }
            }
        }
    }

    // FC: flat index f = o*1024 + y*32 + x0 + xi
    float facc[6];
    #pragma unroll
    for (int j = 0; j < 6; j++) facc[j] = 0.0f;
    const int base = y * 32 + x0;
    #pragma unroll
    for (int j = 0; j < 6; j++) {
        const float* wj = fc_w + (size_t)j * 16384 + base;
        #pragma unroll
        for (int o = 0; o < 16; o++) {
            float4 w4 = *reinterpret_cast<const float4*>(wj + o * 1024);
            facc[j] = fmaf(cacc[0][o], w4.x,
                      fmaf(cacc[1][o], w4.y,
                      fmaf(cacc[2][o], w4.z,
                      fmaf(cacc[3][o], w4.w, facc[j]))));
        }
    }

    #pragma unroll
    for (int j = 0; j < 6; j++) {
        float v = facc[j];
        #pragma unroll
        for (int off = 16; off > 0; off >>= 1)
            v += __shfl_down_sync(0xffffffffu, v, off);
        if ((tid & 31) == 0) sred[(tid >> 5) * 6 + j] = v;
    }
    __syncthreads();
    if (tid < 6) {
        float s = fc_b[tid];
        #pragma unroll
        for (int w = 0; w < 8; w++) s += sred[w * 6 + tid];
        slog[tid] = s;
    }
    __syncthreads();
    if (tid == 0) {
        float mx = slog[0];
        #pragma unroll
        for (int j = 1; j < 6; j++) mx = fmaxf(mx, slog[j]);
        float e[6], s = 0.0f;
        #pragma unroll
        for (int j = 0; j < 6; j++) { e[j] = expf(slog[j] - mx); s += e[j]; }
        float inv = 1.0f / s;
        #pragma unroll
        for (int j = 0; j < 6; j++) out[b * 6 + j] = e[j] * inv;
    }
}

// ===========================================================================
extern "C" void kernel_launch(void* const* d_in, const int* in_sizes, int n_in,
                              void* d_out, int out_size)
{
    const float* x     = (const float*)d_in[0];
    const float* k1    = (const float*)d_in[1];
    const float* gamma = (const float*)d_in[2];
    const float* beta  = (const float*)d_in[3];
    const float* k2    = (const float*)d_in[4];
    const float* k3    = (const float*)d_in[5];
    const float* fc_w  = (const float*)d_in[6];
    const float* fc_b  = (const float*)d_in[7];
    float* out = (float*)d_out;

    k1_conv_bn_pool<<<dim3(4, 8, BATCH), 192>>>(x, k1, gamma, beta);
    k2_conv_pool<<<dim3(2, 4, BATCH), 192>>>(k2);
    k3_conv_fc_softmax<<<BATCH, 256>>>(k3, fc_w, fc_b, out);
}